// round 7
// baseline (speedup 1.0000x reference)
#include <cuda_runtime.h>
#include <math_constants.h>

constexpr int BS  = 128;
constexpr int SEQ = 4096;
constexpr int HID = 128;
constexpr int TOTR = BS * SEQ;                // 524288 global rows
constexpr int THREADS = 1024;
constexpr int WARPS = 32;
constexpr int MAXC = 4;                       // max contributors per batch
constexpr int SMEM_ROWS = 3584;               // >= ceil(TOTR/G) for G >= 147

// Per-batch split-softmax scratch + handshake counters (zero-initialized)
__device__ float    g_pm[BS * MAXC];
__device__ float    g_pl[BS * MAXC];
__device__ float    g_pacc[BS * MAXC * HID];
__device__ unsigned g_cnt[BS];
__device__ unsigned g_done[BS];

// Persistent kernel: grid = #SMs, each CTA owns a contiguous chunk of global
// rows (balanced to within 1 row). A chunk spans <= 2 batches -> at most 2
// segments; per batch <= MAXC contributing CTAs combine via L2 scratch with a
// per-batch counter handshake (all CTAs co-resident: grid <= #SMs).
__global__ __launch_bounds__(THREADS, 1)
void attn_persistent(const float* __restrict__ dec,
                     const float* __restrict__ enc,   // [TOTR, HID]
                     float* __restrict__ attn,        // [TOTR] flat
                     float* __restrict__ ctx)         // [BS, HID]
{
    __shared__ float s_scores[SMEM_ROWS];
    __shared__ float s_m[WARPS], s_l[WARPS];
    __shared__ float s_acc[WARPS][HID];

    const int G    = gridDim.x;
    const int tid  = threadIdx.x;
    const int w    = tid >> 5;
    const int lane = tid & 31;
    const int sub  = lane >> 4;               // 0/1: row parity within group
    const int i    = lane & 15;               // hidden chunk index

    const long long start = (long long)blockIdx.x * TOTR / G;
    const long long end   = (long long)(blockIdx.x + 1) * TOTR / G;

    int seg_b[2], seg_s[2], seg_e[2], seg_c[2], seg_n[2];
    int nseg = 0;

    // ---------------- Phase 1: score pass per batch-segment ----------------
    for (long long s0 = start; s0 < end; ) {
        const int b = (int)(s0 / SEQ);
        const long long be = (long long)(b + 1) * SEQ;
        const int s = (int)s0;
        const int e = (int)(end < be ? end : be);

        // contributor bookkeeping for batch b
        const long long r0 = (long long)b * SEQ;
        const int first = (int)(((r0 + 1) * G - 1) / TOTR);
        const int last  = (int)(((r0 + SEQ) * G - 1) / TOTR);
        const int n = last - first + 1;
        const int c = blockIdx.x - first;

        seg_b[nseg] = b; seg_s[nseg] = s; seg_e[nseg] = e;
        seg_c[nseg] = c; seg_n[nseg] = n; ++nseg;

        const float* dec_b = dec + (size_t)b * HID;
        const float4 d0 = *reinterpret_cast<const float4*>(dec_b + i * 4);
        const float4 d1 = *reinterpret_cast<const float4*>(dec_b + 64 + i * 4);

        float m = -CUDART_INF_F;
        float l = 0.0f;
        float4 acc0 = make_float4(0.f, 0.f, 0.f, 0.f);
        float4 acc1 = make_float4(0.f, 0.f, 0.f, 0.f);

        for (int gb = s + w * 4; gb < e; gb += WARPS * 4) {
            const int rA = gb + sub;
            const int rB = gb + 2 + sub;
            const bool vA = rA < e;
            const bool vB = rB < e;
            const float* pA = enc + (size_t)(vA ? rA : (TOTR - 1)) * HID;
            const float* pB = enc + (size_t)(vB ? rB : (TOTR - 1)) * HID;

            float4 e00 = *reinterpret_cast<const float4*>(pA + i * 4);
            float4 e01 = *reinterpret_cast<const float4*>(pA + 64 + i * 4);
            float4 e10 = *reinterpret_cast<const float4*>(pB + i * 4);
            float4 e11 = *reinterpret_cast<const float4*>(pB + 64 + i * 4);

            float scA = e00.x * d0.x + e00.y * d0.y + e00.z * d0.z + e00.w * d0.w
                      + e01.x * d1.x + e01.y * d1.y + e01.z * d1.z + e01.w * d1.w;
            float scB = e10.x * d0.x + e10.y * d0.y + e10.z * d0.z + e10.w * d0.w
                      + e11.x * d1.x + e11.y * d1.y + e11.z * d1.z + e11.w * d1.w;

            #pragma unroll
            for (int off = 8; off >= 1; off >>= 1) {
                scA += __shfl_xor_sync(0xFFFFFFFFu, scA, off);
                scB += __shfl_xor_sync(0xFFFFFFFFu, scB, off);
            }
            if (!vA) scA = -CUDART_INF_F;
            if (!vB) scB = -CUDART_INF_F;

            if (i == 0) {
                if (vA) s_scores[rA - (int)start] = scA;
                if (vB) s_scores[rB - (int)start] = scB;
            }

            if (scA > m) {
                float cs = __expf(m - scA);
                m = scA; l *= cs;
                acc0.x *= cs; acc0.y *= cs; acc0.z *= cs; acc0.w *= cs;
                acc1.x *= cs; acc1.y *= cs; acc1.z *= cs; acc1.w *= cs;
            }
            if (vA) {
                float p = __expf(scA - m);
                l += p;
                acc0.x += p * e00.x; acc0.y += p * e00.y;
                acc0.z += p * e00.z; acc0.w += p * e00.w;
                acc1.x += p * e01.x; acc1.y += p * e01.y;
                acc1.z += p * e01.z; acc1.w += p * e01.w;
            }
            if (scB > m) {
                float cs = __expf(m - scB);
                m = scB; l *= cs;
                acc0.x *= cs; acc0.y *= cs; acc0.z *= cs; acc0.w *= cs;
                acc1.x *= cs; acc1.y *= cs; acc1.z *= cs; acc1.w *= cs;
            }
            if (vB) {
                float p = __expf(scB - m);
                l += p;
                acc0.x += p * e10.x; acc0.y += p * e10.y;
                acc0.z += p * e10.z; acc0.w += p * e10.w;
                acc1.x += p * e11.x; acc1.y += p * e11.y;
                acc1.z += p * e11.z; acc1.w += p * e11.w;
            }
        }

        // cross-sub combine (one shuffle level)
        float m_o = __shfl_xor_sync(0xFFFFFFFFu, m, 16);
        float l_o = __shfl_xor_sync(0xFFFFFFFFu, l, 16);
        float Mw = fmaxf(m, m_o);
        // guard: empty warp (m == m_o == -inf) -> scales 0, Lw 0
        float sSelf  = (m   == -CUDART_INF_F) ? 0.f : __expf(m - Mw);
        float sOther = (m_o == -CUDART_INF_F) ? 0.f : __expf(m_o - Mw);
        float Lw = l * sSelf + l_o * sOther;

        float a;
        #define XS(v) (__shfl_xor_sync(0xFFFFFFFFu, (v), 16))
        if (true) {
            float t;
            t = XS(acc0.x); if (sub == 0) acc0.x = acc0.x * sSelf + t * sOther;
            t = XS(acc0.y); if (sub == 0) acc0.y = acc0.y * sSelf + t * sOther;
            t = XS(acc0.z); if (sub == 0) acc0.z = acc0.z * sSelf + t * sOther;
            t = XS(acc0.w); if (sub == 0) acc0.w = acc0.w * sSelf + t * sOther;
            t = XS(acc1.x); if (sub == 0) acc1.x = acc1.x * sSelf + t * sOther;
            t = XS(acc1.y); if (sub == 0) acc1.y = acc1.y * sSelf + t * sOther;
            t = XS(acc1.z); if (sub == 0) acc1.z = acc1.z * sSelf + t * sOther;
            t = XS(acc1.w); if (sub == 0) acc1.w = acc1.w * sSelf + t * sOther;
        }
        #undef XS
        (void)a;

        if (sub == 0) {
            *reinterpret_cast<float4*>(&s_acc[w][i * 4])      = acc0;
            *reinterpret_cast<float4*>(&s_acc[w][64 + i * 4]) = acc1;
        }
        if (lane == 0) { s_m[w] = Mw; s_l[w] = Lw; }
        __syncthreads();

        // CTA combine (redundant per thread)
        float M = -CUDART_INF_F;
        #pragma unroll
        for (int j = 0; j < WARPS; ++j) M = fmaxf(M, s_m[j]);
        float L = 0.0f;
        #pragma unroll
        for (int j = 0; j < WARPS; ++j)
            L += s_l[j] * ((s_m[j] == -CUDART_INF_F) ? 0.f : __expf(s_m[j] - M));

        const int slot = b * MAXC + c;
        if (tid == 0) { g_pm[slot] = M; g_pl[slot] = L; }
        if (tid < HID) {
            float cc = 0.0f;
            #pragma unroll
            for (int j = 0; j < WARPS; ++j) {
                float sc = (s_m[j] == -CUDART_INF_F) ? 0.f : __expf(s_m[j] - M);
                cc += s_acc[j][tid] * sc;
            }
            g_pacc[(size_t)slot * HID + tid] = cc;
        }
        __syncthreads();                       // s_m/s_acc reusable next segment
        if (tid == 0) {
            __threadfence();                   // publish partials
            atomicAdd(&g_cnt[b], 1u);
        }

        s0 = e;
    }

    // ---------------- Phase 2: combine + normalize own rows ----------------
    for (int k = 0; k < nseg; ++k) {
        const int b = seg_b[k], s = seg_s[k], e = seg_e[k];
        const int c = seg_c[k], n = seg_n[k];

        if (tid == 0) {
            while (atomicAdd(&g_cnt[b], 0u) < (unsigned)n) __nanosleep(64);
        }
        __syncthreads();

        float pm[MAXC], pl[MAXC];
        for (int j = 0; j < n; ++j) {
            pm[j] = __ldcg(&g_pm[b * MAXC + j]);
            pl[j] = __ldcg(&g_pl[b * MAXC + j]);
        }
        float M = pm[0];
        for (int j = 1; j < n; ++j) M = fmaxf(M, pm[j]);
        float L = 0.0f;
        for (int j = 0; j < n; ++j) L += pl[j] * __expf(pm[j] - M);
        const float invL = 1.0f / L;

        if (c == 0 && tid < HID) {
            float cc = 0.0f;
            for (int j = 0; j < n; ++j)
                cc += __ldcg(&g_pacc[(size_t)(b * MAXC + j) * HID + tid])
                      * __expf(pm[j] - M);
            ctx[(size_t)b * HID + tid] = cc * invL;
        }

        for (int idx = s + tid; idx < e; idx += THREADS) {
            attn[idx] = __expf(s_scores[idx - (int)start] - M) * invL;
        }
        __syncthreads();
        if (tid == 0) atomicAdd(&g_done[b], 1u);
    }

    // reset counters for next graph replay (first contributor of each batch)
    for (int k = 0; k < nseg; ++k) {
        if (seg_c[k] == 0 && tid == 0) {
            const int b = seg_b[k];
            while (atomicAdd(&g_done[b], 0u) < (unsigned)seg_n[k]) __nanosleep(64);
            atomicExch(&g_cnt[b], 0u);
            atomicExch(&g_done[b], 0u);
        }
    }
}

extern "C" void kernel_launch(void* const* d_in, const int* in_sizes, int n_in,
                              void* d_out, int out_size)
{
    const float* dec = (const float*)d_in[0];
    const float* enc = (const float*)d_in[1];
    if (n_in >= 2 && in_sizes[0] > in_sizes[1]) {
        dec = (const float*)d_in[1];
        enc = (const float*)d_in[0];
    }

    float* attn = (float*)d_out;                   // [BS*SEQ] flat
    float* ctx  = attn + (size_t)BS * SEQ;         // [BS, HID]

    int dev = 0, sms = 148;
    cudaGetDevice(&dev);
    cudaDeviceGetAttribute(&sms, cudaDevAttrMultiProcessorCount, dev);
    if (sms < 147) sms = 147;                      // SMEM_ROWS bound guard
    if (sms > 256) sms = 256;

    attn_persistent<<<sms, THREADS>>>(dec, enc, attn, ctx);
}

// round 8
// speedup vs baseline: 1.0680x; 1.0680x over previous
#include <cuda_runtime.h>
#include <math_constants.h>

constexpr int BS   = 128;
constexpr int SEQ  = 4096;
constexpr int HID  = 128;
constexpr int TOTR = BS * SEQ;              // 524288 rows
constexpr int GROUPS = TOTR / 4;            // 131072 4-row groups
constexpr int GPB    = SEQ / 4;             // 1024 groups per batch
constexpr int THREADS = 1024;
constexpr int WARPS   = 32;
constexpr int MAXC    = 4;                  // max contributors per batch
constexpr int SMEM_ROWS = 3584;             // >= ceil(GROUPS/G)*4 for G >= 147

// Per-batch split-softmax scratch + handshake (zero-initialized, reset in-kernel)
__device__ float    g_pm[BS * MAXC];
__device__ float    g_pl[BS * MAXC];
__device__ float    g_pacc[BS * MAXC * HID];
__device__ unsigned g_cnt[BS];
__device__ unsigned g_done[BS];

// Persistent kernel, grid = #SMs. Work is partitioned in 4-row GROUPS so every
// segment boundary is group-aligned: the streaming inner loop is branchless
// (identical to the best R6 body). A CTA's chunk spans <= 2 batches; per batch
// <= MAXC contributing CTAs combine softmax partials via L2 + counter.
__global__ __launch_bounds__(THREADS, 1)
void attn_persistent(const float* __restrict__ dec,
                     const float* __restrict__ enc,   // [TOTR, HID]
                     float* __restrict__ attn,        // [TOTR] flat probs
                     float* __restrict__ ctx)         // [BS, HID]
{
    __shared__ float s_scores[SMEM_ROWS];             // 14 KB
    __shared__ float s_m[WARPS], s_l[WARPS];
    __shared__ float s_acc[WARPS][HID];               // 16 KB

    const int G    = gridDim.x;
    const int bid  = blockIdx.x;
    const int tid  = threadIdx.x;
    const int w    = tid >> 5;
    const int lane = tid & 31;
    const int sub  = lane >> 4;                       // row parity in group
    const int i    = lane & 15;                       // hidden chunk index

    const int gs = (int)((long long)bid * GROUPS / G);        // first group
    const int ge = (int)((long long)(bid + 1) * GROUPS / G);  // end group
    const int startRow = gs * 4;

    // segment bookkeeping (<= 2 segments), kept in scalars
    int sb0 = -1, ss0 = 0, se0 = 0, sc0 = 0, sn0 = 0;
    int sb1 = -1, ss1 = 0, se1 = 0, sc1 = 0, sn1 = 0;
    int nseg = 0;

    for (int seg_s = gs; seg_s < ge; ) {
        const int b  = seg_s / GPB;
        const int bEnd = (b + 1) * GPB;
        const int seg_e = ge < bEnd ? ge : bEnd;

        // contributors to batch b:  owner(g) = (g*G + G - 1) / GROUPS
        const int first = (int)(((long long)(b * GPB) * G + G - 1) / GROUPS);
        const int last  = (int)(((long long)(bEnd - 1) * G + G - 1) / GROUPS);
        const int n = last - first + 1;
        const int c = bid - first;

        if (nseg == 0) { sb0 = b; ss0 = seg_s; se0 = seg_e; sc0 = c; sn0 = n; }
        else           { sb1 = b; ss1 = seg_s; se1 = seg_e; sc1 = c; sn1 = n; }
        ++nseg;

        const float* dec_b = dec + (size_t)b * HID;
        const float4 d0 = *reinterpret_cast<const float4*>(dec_b + i * 4);
        const float4 d1 = *reinterpret_cast<const float4*>(dec_b + 64 + i * 4);

        float m = -CUDART_INF_F;
        float l = 0.0f;
        float4 acc0 = make_float4(0.f, 0.f, 0.f, 0.f);
        float4 acc1 = make_float4(0.f, 0.f, 0.f, 0.f);

        // ---- branchless streaming loop: one 4-row group per warp-iter ----
        for (int grp = seg_s + w; grp < seg_e; grp += WARPS) {
            const int base = grp * 4;
            const float* pA = enc + (size_t)(base + sub) * HID;
            const float* pB = enc + (size_t)(base + 2 + sub) * HID;

            float4 e00 = *reinterpret_cast<const float4*>(pA + i * 4);
            float4 e01 = *reinterpret_cast<const float4*>(pA + 64 + i * 4);
            float4 e10 = *reinterpret_cast<const float4*>(pB + i * 4);
            float4 e11 = *reinterpret_cast<const float4*>(pB + 64 + i * 4);

            float scA = e00.x * d0.x + e00.y * d0.y + e00.z * d0.z + e00.w * d0.w
                      + e01.x * d1.x + e01.y * d1.y + e01.z * d1.z + e01.w * d1.w;
            float scB = e10.x * d0.x + e10.y * d0.y + e10.z * d0.z + e10.w * d0.w
                      + e11.x * d1.x + e11.y * d1.y + e11.z * d1.z + e11.w * d1.w;

            #pragma unroll
            for (int off = 8; off >= 1; off >>= 1) {
                scA += __shfl_xor_sync(0xFFFFFFFFu, scA, off);
                scB += __shfl_xor_sync(0xFFFFFFFFu, scB, off);
            }

            if (i == 0) {
                s_scores[base + sub - startRow]     = scA;
                s_scores[base + 2 + sub - startRow] = scB;
            }

            if (scA > m) {
                float cs = __expf(m - scA);           // exp(-inf)=0 first time
                m = scA; l *= cs;
                acc0.x *= cs; acc0.y *= cs; acc0.z *= cs; acc0.w *= cs;
                acc1.x *= cs; acc1.y *= cs; acc1.z *= cs; acc1.w *= cs;
            }
            float pAe = __expf(scA - m);
            l += pAe;
            acc0.x += pAe * e00.x; acc0.y += pAe * e00.y;
            acc0.z += pAe * e00.z; acc0.w += pAe * e00.w;
            acc1.x += pAe * e01.x; acc1.y += pAe * e01.y;
            acc1.z += pAe * e01.z; acc1.w += pAe * e01.w;

            if (scB > m) {
                float cs = __expf(m - scB);
                m = scB; l *= cs;
                acc0.x *= cs; acc0.y *= cs; acc0.z *= cs; acc0.w *= cs;
                acc1.x *= cs; acc1.y *= cs; acc1.z *= cs; acc1.w *= cs;
            }
            float pBe = __expf(scB - m);
            l += pBe;
            acc0.x += pBe * e10.x; acc0.y += pBe * e10.y;
            acc0.z += pBe * e10.z; acc0.w += pBe * e10.w;
            acc1.x += pBe * e11.x; acc1.y += pBe * e11.y;
            acc1.z += pBe * e11.z; acc1.w += pBe * e11.w;
        }

        // ---- epilogue (once per segment; -inf-safe) ----
        float m_o = __shfl_xor_sync(0xFFFFFFFFu, m, 16);
        float l_o = __shfl_xor_sync(0xFFFFFFFFu, l, 16);
        float Mw = fmaxf(m, m_o);
        float sSelf  = (m   == -CUDART_INF_F) ? 0.f : __expf(m - Mw);
        float sOther = (m_o == -CUDART_INF_F) ? 0.f : __expf(m_o - Mw);
        float Lw = l * sSelf + l_o * sOther;

        float t;
        t = __shfl_xor_sync(0xFFFFFFFFu, acc0.x, 16); acc0.x = acc0.x * sSelf + t * sOther;
        t = __shfl_xor_sync(0xFFFFFFFFu, acc0.y, 16); acc0.y = acc0.y * sSelf + t * sOther;
        t = __shfl_xor_sync(0xFFFFFFFFu, acc0.z, 16); acc0.z = acc0.z * sSelf + t * sOther;
        t = __shfl_xor_sync(0xFFFFFFFFu, acc0.w, 16); acc0.w = acc0.w * sSelf + t * sOther;
        t = __shfl_xor_sync(0xFFFFFFFFu, acc1.x, 16); acc1.x = acc1.x * sSelf + t * sOther;
        t = __shfl_xor_sync(0xFFFFFFFFu, acc1.y, 16); acc1.y = acc1.y * sSelf + t * sOther;
        t = __shfl_xor_sync(0xFFFFFFFFu, acc1.z, 16); acc1.z = acc1.z * sSelf + t * sOther;
        t = __shfl_xor_sync(0xFFFFFFFFu, acc1.w, 16); acc1.w = acc1.w * sSelf + t * sOther;

        if (sub == 0) {
            *reinterpret_cast<float4*>(&s_acc[w][i * 4])      = acc0;
            *reinterpret_cast<float4*>(&s_acc[w][64 + i * 4]) = acc1;
        }
        if (lane == 0) { s_m[w] = Mw; s_l[w] = Lw; }
        __syncthreads();

        float M = -CUDART_INF_F;
        #pragma unroll
        for (int j = 0; j < WARPS; ++j) M = fmaxf(M, s_m[j]);
        float L = 0.0f;
        #pragma unroll
        for (int j = 0; j < WARPS; ++j) {
            float sc = (s_m[j] == -CUDART_INF_F) ? 0.f : __expf(s_m[j] - M);
            L += s_l[j] * sc;
        }

        const int slot = b * MAXC + c;
        if (tid == 0) { g_pm[slot] = M; g_pl[slot] = L; }
        if (tid < HID) {
            float cc = 0.0f;
            #pragma unroll
            for (int j = 0; j < WARPS; ++j) {
                float sc = (s_m[j] == -CUDART_INF_F) ? 0.f : __expf(s_m[j] - M);
                cc += s_acc[j][tid] * sc;
            }
            g_pacc[(size_t)slot * HID + tid] = cc;
        }
        __syncthreads();                        // s_m/s_acc reusable
        if (tid == 0) {
            __threadfence();                    // publish partials to L2
            atomicAdd(&g_cnt[b], 1u);
        }

        seg_s = seg_e;
    }

    // ---------------- Phase 2: combine + normalize own rows ----------------
    #pragma unroll
    for (int k = 0; k < 2; ++k) {
        if (k >= nseg) break;
        const int b = k ? sb1 : sb0;
        const int s = (k ? ss1 : ss0) * 4;
        const int e = (k ? se1 : se0) * 4;
        const int c = k ? sc1 : sc0;
        const int n = k ? sn1 : sn0;

        if (tid == 0) {
            while (atomicAdd(&g_cnt[b], 0u) < (unsigned)n) __nanosleep(32);
        }
        __syncthreads();

        float pm[MAXC], pl[MAXC];
        for (int j = 0; j < n; ++j) {
            pm[j] = __ldcg(&g_pm[b * MAXC + j]);
            pl[j] = __ldcg(&g_pl[b * MAXC + j]);
        }
        float M = pm[0];
        for (int j = 1; j < n; ++j) M = fmaxf(M, pm[j]);
        float L = 0.0f;
        for (int j = 0; j < n; ++j) L += pl[j] * __expf(pm[j] - M);
        const float invL = 1.0f / L;

        if (c == 0 && tid < HID) {
            float cc = 0.0f;
            for (int j = 0; j < n; ++j)
                cc += __ldcg(&g_pacc[(size_t)(b * MAXC + j) * HID + tid])
                      * __expf(pm[j] - M);
            ctx[(size_t)b * HID + tid] = cc * invL;
        }

        for (int idx = s + tid; idx < e; idx += THREADS) {
            attn[idx] = __expf(s_scores[idx - startRow] - M) * invL;
        }
        __syncthreads();
        if (tid == 0) atomicAdd(&g_done[b], 1u);
    }

    // reset per-batch counters for next graph replay (contributor 0 of each batch)
    if (tid == 0) {
        if (nseg >= 1 && sc0 == 0) {
            while (atomicAdd(&g_done[sb0], 0u) < (unsigned)sn0) __nanosleep(32);
            atomicExch(&g_cnt[sb0], 0u);
            atomicExch(&g_done[sb0], 0u);
        }
        if (nseg >= 2 && sc1 == 0) {
            while (atomicAdd(&g_done[sb1], 0u) < (unsigned)sn1) __nanosleep(32);
            atomicExch(&g_cnt[sb1], 0u);
            atomicExch(&g_done[sb1], 0u);
        }
    }
}

extern "C" void kernel_launch(void* const* d_in, const int* in_sizes, int n_in,
                              void* d_out, int out_size)
{
    const float* dec = (const float*)d_in[0];
    const float* enc = (const float*)d_in[1];
    if (n_in >= 2 && in_sizes[0] > in_sizes[1]) {
        dec = (const float*)d_in[1];
        enc = (const float*)d_in[0];
    }

    float* attn = (float*)d_out;                   // [BS*SEQ] flat
    float* ctx  = attn + (size_t)BS * SEQ;         // [BS, HID]

    int dev = 0, sms = 148;
    cudaGetDevice(&dev);
    cudaDeviceGetAttribute(&sms, cudaDevAttrMultiProcessorCount, dev);
    if (sms < 147) sms = 147;                      // SMEM_ROWS coverage guard
    if (sms > 192) sms = 192;

    attn_persistent<<<sms, THREADS>>>(dec, enc, attn, ctx);
}

// round 9
// speedup vs baseline: 1.1124x; 1.0416x over previous
#include <cuda_runtime.h>
#include <math_constants.h>

// Problem shape (fixed by reference setup_inputs)
constexpr int BS  = 128;
constexpr int SEQ = 4096;
constexpr int HID = 128;

constexpr int WARPS   = 32;
constexpr int THREADS = WARPS * 32;          // 1024
constexpr int ROWS_PER_WARP = SEQ / WARPS;   // 128

// One CTA per batch, 32 warps. 16 lanes per row (sub = row parity, i = hidden
// chunk). 2-row groups with explicit depth-1 prefetch so every warp keeps its
// next 2 LDG.128s in flight while computing the current group — sustained MLP
// instead of the bursty load-then-stall pattern of the 4-row version.
__global__ __launch_bounds__(THREADS, 1)
void seq2seq_attn_kernel(const float* __restrict__ dec,
                         const float* __restrict__ enc,
                         float* __restrict__ attn,   // [BS, SEQ]
                         float* __restrict__ ctx)    // [BS, HID]
{
    __shared__ float s_scores[SEQ];                 // 16 KB raw scores
    __shared__ float s_m[WARPS];
    __shared__ float s_l[WARPS];
    __shared__ float s_acc[WARPS][HID];             // 16 KB partial contexts

    const int b    = blockIdx.x;
    const int tid  = threadIdx.x;
    const int w    = tid >> 5;
    const int lane = tid & 31;
    const int sub  = lane >> 4;                     // 0/1: row parity
    const int i    = lane & 15;                     // hidden chunk index

    const float* dec_b = dec + (size_t)b * HID;
    const float4 d0 = *reinterpret_cast<const float4*>(dec_b + i * 4);
    const float4 d1 = *reinterpret_cast<const float4*>(dec_b + 64 + i * 4);

    const float* enc_b = enc + (size_t)b * SEQ * HID;

    float m = -CUDART_INF_F;
    float l = 0.0f;
    float4 acc0 = make_float4(0.f, 0.f, 0.f, 0.f);
    float4 acc1 = make_float4(0.f, 0.f, 0.f, 0.f);

    const int row0 = w * ROWS_PER_WARP;

    // lane's streaming pointer: row (row0+sub), hidden chunk i
    const float* p = enc_b + (size_t)(row0 + sub) * HID;

    // prefetch group 0 (streaming loads: no L2 retention needed)
    float4 nA = __ldcs(reinterpret_cast<const float4*>(p + i * 4));
    float4 nB = __ldcs(reinterpret_cast<const float4*>(p + 64 + i * 4));

    #pragma unroll 2
    for (int r = row0; r < row0 + ROWS_PER_WARP; r += 2) {
        // consume prefetched regs, immediately issue next group's loads
        const float4 eA = nA;
        const float4 eB = nB;
        p += 2 * HID;
        if (r + 2 < row0 + ROWS_PER_WARP) {
            nA = __ldcs(reinterpret_cast<const float4*>(p + i * 4));
            nB = __ldcs(reinterpret_cast<const float4*>(p + 64 + i * 4));
        }

        // dot partial over this lane's 8 hidden components
        float sc = eA.x * d0.x + eA.y * d0.y + eA.z * d0.z + eA.w * d0.w
                 + eB.x * d1.x + eB.y * d1.y + eB.z * d1.z + eB.w * d1.w;

        // 4-level butterfly within the 16-lane row group
        #pragma unroll
        for (int off = 8; off >= 1; off >>= 1)
            sc += __shfl_xor_sync(0xFFFFFFFFu, sc, off);

        if (i == 0) s_scores[r + sub] = sc;         // lanes 0 and 16

        // branch-guarded online softmax + context accumulation
        if (sc > m) {
            float cs = __expf(m - sc);              // exp(-inf)=0 first time
            m = sc; l *= cs;
            acc0.x *= cs; acc0.y *= cs; acc0.z *= cs; acc0.w *= cs;
            acc1.x *= cs; acc1.y *= cs; acc1.z *= cs; acc1.w *= cs;
        }
        float pe = __expf(sc - m);
        l += pe;
        acc0.x += pe * eA.x; acc0.y += pe * eA.y;
        acc0.z += pe * eA.z; acc0.w += pe * eA.w;
        acc1.x += pe * eB.x; acc1.y += pe * eB.y;
        acc1.z += pe * eB.z; acc1.w += pe * eB.w;
    }

    // ---- cross-sub combine (one butterfly level, once per warp) ----
    float m_o = __shfl_xor_sync(0xFFFFFFFFu, m, 16);
    float l_o = __shfl_xor_sync(0xFFFFFFFFu, l, 16);
    float Mw = fmaxf(m, m_o);
    float sSelf  = __expf(m - Mw);
    float sOther = __expf(m_o - Mw);
    float Lw = l * sSelf + l_o * sOther;

    float t;
    t = __shfl_xor_sync(0xFFFFFFFFu, acc0.x, 16); acc0.x = acc0.x * sSelf + t * sOther;
    t = __shfl_xor_sync(0xFFFFFFFFu, acc0.y, 16); acc0.y = acc0.y * sSelf + t * sOther;
    t = __shfl_xor_sync(0xFFFFFFFFu, acc0.z, 16); acc0.z = acc0.z * sSelf + t * sOther;
    t = __shfl_xor_sync(0xFFFFFFFFu, acc0.w, 16); acc0.w = acc0.w * sSelf + t * sOther;
    t = __shfl_xor_sync(0xFFFFFFFFu, acc1.x, 16); acc1.x = acc1.x * sSelf + t * sOther;
    t = __shfl_xor_sync(0xFFFFFFFFu, acc1.y, 16); acc1.y = acc1.y * sSelf + t * sOther;
    t = __shfl_xor_sync(0xFFFFFFFFu, acc1.z, 16); acc1.z = acc1.z * sSelf + t * sOther;
    t = __shfl_xor_sync(0xFFFFFFFFu, acc1.w, 16); acc1.w = acc1.w * sSelf + t * sOther;

    if (sub == 0) {                                 // lanes 0..15 hold warp totals
        *reinterpret_cast<float4*>(&s_acc[w][i * 4])      = acc0;
        *reinterpret_cast<float4*>(&s_acc[w][64 + i * 4]) = acc1;
    }
    if (lane == 0) { s_m[w] = Mw; s_l[w] = Lw; }
    __syncthreads();

    // ---- CTA combine: every thread redundantly folds 32 warp partials ----
    float M = -CUDART_INF_F;
    #pragma unroll
    for (int j = 0; j < WARPS; ++j) M = fmaxf(M, s_m[j]);
    float L = 0.0f;
    #pragma unroll
    for (int j = 0; j < WARPS; ++j) L += s_l[j] * __expf(s_m[j] - M);
    const float invL = 1.0f / L;

    // context: threads 0..127 each own one hidden component
    if (tid < HID) {
        float c = 0.0f;
        #pragma unroll
        for (int j = 0; j < WARPS; ++j) c += s_acc[j][tid] * __expf(s_m[j] - M);
        ctx[(size_t)b * HID + tid] = c * invL;
    }

    // attn_prob: normalize parked scores, one float4 per thread (coalesced)
    {
        float4 v = *reinterpret_cast<const float4*>(&s_scores[tid * 4]);
        v.x = __expf(v.x - M) * invL;
        v.y = __expf(v.y - M) * invL;
        v.z = __expf(v.z - M) * invL;
        v.w = __expf(v.w - M) * invL;
        *reinterpret_cast<float4*>(attn + (size_t)b * SEQ + tid * 4) = v;
    }
}

extern "C" void kernel_launch(void* const* d_in, const int* in_sizes, int n_in,
                              void* d_out, int out_size)
{
    const float* dec = (const float*)d_in[0];
    const float* enc = (const float*)d_in[1];
    if (n_in >= 2 && in_sizes[0] > in_sizes[1]) {
        dec = (const float*)d_in[1];
        enc = (const float*)d_in[0];
    }

    float* attn = (float*)d_out;                   // [BS, SEQ]
    float* ctx  = attn + (size_t)BS * SEQ;         // [BS, HID]

    seq2seq_attn_kernel<<<BS, THREADS>>>(dec, enc, attn, ctx);
}

// round 12
// speedup vs baseline: 1.2049x; 1.0831x over previous
#include <cuda_runtime.h>
#include <math_constants.h>
#include <cstdint>

constexpr int BS  = 128;
constexpr int SEQ = 4096;
constexpr int HID = 128;

constexpr int WARPS   = 32;
constexpr int THREADS = WARPS * 32;            // 1024
constexpr int TROWS   = 64;                    // rows per tile
constexpr int NT      = SEQ / TROWS;           // 64 tiles
constexpr int STAGES  = 3;
constexpr int TILE_F  = TROWS * HID;           // 8192 floats = 32 KB

// dynamic smem layout (floats):
//   [0, STAGES*TILE_F)          tile ring buffers (96 KB)
//   [+0, SEQ)                   raw scores (16 KB)
//   [+0, WARPS*HID)             per-warp context partials (16 KB)
//   [+0, WARPS)                 per-warp m
//   [+0, WARPS)                 per-warp l
constexpr int SMEM_FLOATS = STAGES * TILE_F + SEQ + WARPS * HID + 2 * WARPS;
constexpr size_t SMEM_BYTES = (size_t)SMEM_FLOATS * 4;

__device__ __forceinline__ void cp16(float* dst, const float* src) {
    uint32_t sa = (uint32_t)__cvta_generic_to_shared(dst);
    asm volatile("cp.async.cg.shared.global [%0], [%1], 16;\n"
                 :: "r"(sa), "l"(src));
}

// One CTA per batch. Producer/consumer via cp.async: loads stream into a
// 3-stage smem ring (2 tiles always in flight), compute consumes from smem.
// This decouples DRAM issue from the dot/shuffle/exp latency chains that
// throttled the register-resident versions.
__global__ __launch_bounds__(THREADS, 1)
void seq2seq_attn_kernel(const float* __restrict__ dec,
                         const float* __restrict__ enc,
                         float* __restrict__ attn,   // [BS, SEQ]
                         float* __restrict__ ctx)    // [BS, HID]
{
    extern __shared__ float smem[];
    float* s_buf    = smem;
    float* s_scores = s_buf + STAGES * TILE_F;
    float* s_acc    = s_scores + SEQ;               // [WARPS][HID]
    float* s_m      = s_acc + WARPS * HID;
    float* s_l      = s_m + WARPS;

    const int b    = blockIdx.x;
    const int tid  = threadIdx.x;
    const int w    = tid >> 5;
    const int lane = tid & 31;
    const int sub  = lane >> 4;                     // row parity within pair
    const int i    = lane & 15;                     // hidden chunk index

    const float* dec_b = dec + (size_t)b * HID;
    const float4 d0 = *reinterpret_cast<const float4*>(dec_b + i * 4);
    const float4 d1 = *reinterpret_cast<const float4*>(dec_b + 64 + i * 4);

    const float* enc_b = enc + (size_t)b * SEQ * HID;

    // issue one tile's cp.asyncs (each thread copies 2x16B; 1024*2*16B = 32KB)
    auto issue_tile = [&](int t) {
        const float* src = enc_b + (size_t)t * TILE_F + tid * 4;
        float* dst = s_buf + (t % STAGES) * TILE_F + tid * 4;
        cp16(dst, src);
        cp16(dst + 4096, src + 4096);
    };

    issue_tile(0);
    asm volatile("cp.async.commit_group;\n");
    issue_tile(1);
    asm volatile("cp.async.commit_group;\n");

    float m = -CUDART_INF_F;
    float l = 0.0f;
    float4 acc0 = make_float4(0.f, 0.f, 0.f, 0.f);
    float4 acc1 = make_float4(0.f, 0.f, 0.f, 0.f);

    for (int t = 0; t < NT; ++t) {
        if (t + 2 < NT) issue_tile(t + 2);
        asm volatile("cp.async.commit_group;\n");
        asm volatile("cp.async.wait_group 2;\n");   // tile t landed
        __syncthreads();

        // each warp consumes 2 rows of the tile: rows 2w+0 / 2w+1 via sub
        const float* pr = s_buf + (t % STAGES) * TILE_F + (2 * w + sub) * HID;
        const float4 eA = *reinterpret_cast<const float4*>(pr + i * 4);
        const float4 eB = *reinterpret_cast<const float4*>(pr + 64 + i * 4);

        float sc = eA.x * d0.x + eA.y * d0.y + eA.z * d0.z + eA.w * d0.w
                 + eB.x * d1.x + eB.y * d1.y + eB.z * d1.z + eB.w * d1.w;

        #pragma unroll
        for (int off = 8; off >= 1; off >>= 1)
            sc += __shfl_xor_sync(0xFFFFFFFFu, sc, off);

        if (i == 0) s_scores[t * TROWS + 2 * w + sub] = sc;

        if (sc > m) {
            float cs = __expf(m - sc);              // exp(-inf)=0 first time
            m = sc; l *= cs;
            acc0.x *= cs; acc0.y *= cs; acc0.z *= cs; acc0.w *= cs;
            acc1.x *= cs; acc1.y *= cs; acc1.z *= cs; acc1.w *= cs;
        }
        float pe = __expf(sc - m);
        l += pe;
        acc0.x += pe * eA.x; acc0.y += pe * eA.y;
        acc0.z += pe * eA.z; acc0.w += pe * eA.w;
        acc1.x += pe * eB.x; acc1.y += pe * eB.y;
        acc1.z += pe * eB.z; acc1.w += pe * eB.w;

        __syncthreads();                            // buffer reusable
    }

    // ---- cross-sub combine (one butterfly level) ----
    float m_o = __shfl_xor_sync(0xFFFFFFFFu, m, 16);
    float l_o = __shfl_xor_sync(0xFFFFFFFFu, l, 16);
    float Mw = fmaxf(m, m_o);
    float sSelf  = __expf(m - Mw);
    float sOther = __expf(m_o - Mw);
    float Lw = l * sSelf + l_o * sOther;

    float t2;
    t2 = __shfl_xor_sync(0xFFFFFFFFu, acc0.x, 16); acc0.x = acc0.x * sSelf + t2 * sOther;
    t2 = __shfl_xor_sync(0xFFFFFFFFu, acc0.y, 16); acc0.y = acc0.y * sSelf + t2 * sOther;
    t2 = __shfl_xor_sync(0xFFFFFFFFu, acc0.z, 16); acc0.z = acc0.z * sSelf + t2 * sOther;
    t2 = __shfl_xor_sync(0xFFFFFFFFu, acc0.w, 16); acc0.w = acc0.w * sSelf + t2 * sOther;
    t2 = __shfl_xor_sync(0xFFFFFFFFu, acc1.x, 16); acc1.x = acc1.x * sSelf + t2 * sOther;
    t2 = __shfl_xor_sync(0xFFFFFFFFu, acc1.y, 16); acc1.y = acc1.y * sSelf + t2 * sOther;
    t2 = __shfl_xor_sync(0xFFFFFFFFu, acc1.z, 16); acc1.z = acc1.z * sSelf + t2 * sOther;
    t2 = __shfl_xor_sync(0xFFFFFFFFu, acc1.w, 16); acc1.w = acc1.w * sSelf + t2 * sOther;

    if (sub == 0) {
        *reinterpret_cast<float4*>(&s_acc[w * HID + i * 4])      = acc0;
        *reinterpret_cast<float4*>(&s_acc[w * HID + 64 + i * 4]) = acc1;
    }
    if (lane == 0) { s_m[w] = Mw; s_l[w] = Lw; }
    __syncthreads();

    // ---- CTA combine (redundant per thread, cheap) ----
    float M = -CUDART_INF_F;
    #pragma unroll
    for (int j = 0; j < WARPS; ++j) M = fmaxf(M, s_m[j]);
    float L = 0.0f;
    #pragma unroll
    for (int j = 0; j < WARPS; ++j) L += s_l[j] * __expf(s_m[j] - M);
    const float invL = 1.0f / L;

    if (tid < HID) {
        float c = 0.0f;
        #pragma unroll
        for (int j = 0; j < WARPS; ++j) c += s_acc[j * HID + tid] * __expf(s_m[j] - M);
        ctx[(size_t)b * HID + tid] = c * invL;
    }

    // attn probs: one float4 per thread, coalesced
    {
        float4 v = *reinterpret_cast<const float4*>(&s_scores[tid * 4]);
        v.x = __expf(v.x - M) * invL;
        v.y = __expf(v.y - M) * invL;
        v.z = __expf(v.z - M) * invL;
        v.w = __expf(v.w - M) * invL;
        *reinterpret_cast<float4*>(attn + (size_t)b * SEQ + tid * 4) = v;
    }
}

extern "C" void kernel_launch(void* const* d_in, const int* in_sizes, int n_in,
                              void* d_out, int out_size)
{
    const float* dec = (const float*)d_in[0];
    const float* enc = (const float*)d_in[1];
    if (n_in >= 2 && in_sizes[0] > in_sizes[1]) {
        dec = (const float*)d_in[1];
        enc = (const float*)d_in[0];
    }

    float* attn = (float*)d_out;                   // [BS, SEQ]
    float* ctx  = attn + (size_t)BS * SEQ;         // [BS, HID]

    // opt-in to >48KB dynamic smem (idempotent; no allocation involved)
    cudaFuncSetAttribute(seq2seq_attn_kernel,
                         cudaFuncAttributeMaxDynamicSharedMemorySize,
                         (int)SMEM_BYTES);

    seq2seq_attn_kernel<<<BS, THREADS, SMEM_BYTES>>>(dec, enc, attn, ctx);
}

// round 14
// speedup vs baseline: 1.2500x; 1.0374x over previous
#include <cuda_runtime.h>
#include <math_constants.h>
#include <cstdint>

constexpr int BS  = 128;
constexpr int SEQ = 4096;
constexpr int HID = 128;

constexpr int WARPS   = 32;
constexpr int THREADS = WARPS * 32;            // 1024
constexpr int TROWS   = 128;                   // rows per tile
constexpr int NT      = SEQ / TROWS;           // 32 tiles
constexpr int STAGES  = 3;
constexpr int TILE_F  = TROWS * HID;           // 16384 floats = 64 KB
constexpr int TILE_B  = TILE_F * 4;            // 65536 bytes

// dynamic smem layout (floats):
//   [0, STAGES*TILE_F)   tile ring (192 KB)
//   s_scores[SEQ]        raw scores (16 KB)
//   s_acc[WARPS*HID]     per-warp context partials (16 KB)
//   s_m[WARPS], s_l[WARPS]
//   mbar[STAGES] (uint64) at the tail (16B-aligned region)
constexpr int SMEM_FLOATS = STAGES * TILE_F + SEQ + WARPS * HID + 2 * WARPS + 8;
constexpr size_t SMEM_BYTES = (size_t)SMEM_FLOATS * 4;

__device__ __forceinline__ uint32_t smem_u32(const void* p) {
    return (uint32_t)__cvta_generic_to_shared(p);
}

__device__ __forceinline__ void mbar_init(uint32_t mbar, uint32_t cnt) {
    asm volatile("mbarrier.init.shared.b64 [%0], %1;" :: "r"(mbar), "r"(cnt) : "memory");
}
__device__ __forceinline__ void mbar_expect_tx(uint32_t mbar, uint32_t bytes) {
    asm volatile("mbarrier.arrive.expect_tx.shared.b64 _, [%0], %1;"
                 :: "r"(mbar), "r"(bytes) : "memory");
}
__device__ __forceinline__ void mbar_wait(uint32_t mbar, uint32_t phase) {
    asm volatile(
        "{\n\t"
        ".reg .pred P1;\n\t"
        "WAIT_%=:\n\t"
        "mbarrier.try_wait.parity.shared::cta.b64 P1, [%0], %1, 0x989680;\n\t"
        "@P1 bra.uni DONE_%=;\n\t"
        "bra.uni WAIT_%=;\n\t"
        "DONE_%=:\n\t"
        "}"
        :: "r"(mbar), "r"(phase) : "memory");
}
__device__ __forceinline__ void tma_bulk_1d(uint32_t smem_dst, const void* gsrc,
                                            uint32_t bytes, uint32_t mbar) {
    asm volatile(
        "cp.async.bulk.shared::cta.global.mbarrier::complete_tx::bytes "
        "[%0], [%1], %2, [%3];"
        :: "r"(smem_dst), "l"(gsrc), "r"(bytes), "r"(mbar) : "memory");
}

// One CTA per batch. TMA-bulk producer (1 instruction / 64KB tile) + 3-stage
// smem ring; all 32 warps consume 4 rows each per tile with the proven
// 16-lane-per-row mapping. Eliminates the LDGSTS issue tax of the cp.async
// version (2048 ops/tile -> 1 op/tile).
__global__ __launch_bounds__(THREADS, 1)
void seq2seq_attn_kernel(const float* __restrict__ dec,
                         const float* __restrict__ enc,
                         float* __restrict__ attn,   // [BS, SEQ]
                         float* __restrict__ ctx)    // [BS, HID]
{
    extern __shared__ float smem[];
    float* s_buf    = smem;
    float* s_scores = s_buf + STAGES * TILE_F;
    float* s_acc    = s_scores + SEQ;               // [WARPS][HID]
    float* s_m      = s_acc + WARPS * HID;
    float* s_l      = s_m + WARPS;
    // 16B-aligned tail for mbarriers
    uint64_t* mbar64 = reinterpret_cast<uint64_t*>(s_l + WARPS);
    const uint32_t mb0 = smem_u32(mbar64);

    const int b    = blockIdx.x;
    const int tid  = threadIdx.x;
    const int w    = tid >> 5;
    const int lane = tid & 31;
    const int sub  = lane >> 4;                     // 0/1: row parity in pair
    const int i    = lane & 15;                     // hidden chunk index

    const float* dec_b = dec + (size_t)b * HID;
    const float4 d0 = *reinterpret_cast<const float4*>(dec_b + i * 4);
    const float4 d1 = *reinterpret_cast<const float4*>(dec_b + 64 + i * 4);

    const float* enc_b = enc + (size_t)b * SEQ * HID;

    if (tid == 0) {
        #pragma unroll
        for (int s = 0; s < STAGES; ++s) mbar_init(mb0 + 8 * s, 1);
    }
    __syncthreads();                                // mbarriers visible

    // prologue: issue tiles 0..STAGES-2
    if (tid == 0) {
        #pragma unroll
        for (int t = 0; t < STAGES - 1; ++t) {
            mbar_expect_tx(mb0 + 8 * t, TILE_B);
            tma_bulk_1d(smem_u32(s_buf + t * TILE_F),
                        enc_b + (size_t)t * TILE_F, TILE_B, mb0 + 8 * t);
        }
    }

    float m = -CUDART_INF_F;
    float l = 0.0f;
    float4 acc0 = make_float4(0.f, 0.f, 0.f, 0.f);
    float4 acc1 = make_float4(0.f, 0.f, 0.f, 0.f);

    int stg = 0, ph = 0;                            // consumer cursor
    int isg = STAGES - 1;                           // issue stage cursor

    for (int t = 0; t < NT; ++t) {
        // issue tile t+STAGES-1 into stage isg (that stage was consumed at
        // iteration t-1 and recycled by the trailing __syncthreads)
        const int ti = t + STAGES - 1;
        if (tid == 0 && ti < NT) {
            mbar_expect_tx(mb0 + 8 * isg, TILE_B);
            tma_bulk_1d(smem_u32(s_buf + isg * TILE_F),
                        enc_b + (size_t)ti * TILE_F, TILE_B, mb0 + 8 * isg);
        }
        if (++isg == STAGES) isg = 0;

        mbar_wait(mb0 + 8 * stg, (uint32_t)ph);     // tile t landed

        // warp w consumes rows 4w..4w+3 of the tile (two pair-iterations)
        const float* tp = s_buf + stg * TILE_F + (4 * w) * HID;
        const float4 eA0 = *reinterpret_cast<const float4*>(tp + sub * HID + i * 4);
        const float4 eB0 = *reinterpret_cast<const float4*>(tp + sub * HID + 64 + i * 4);
        const float4 eA1 = *reinterpret_cast<const float4*>(tp + (2 + sub) * HID + i * 4);
        const float4 eB1 = *reinterpret_cast<const float4*>(tp + (2 + sub) * HID + 64 + i * 4);

        float scA = eA0.x * d0.x + eA0.y * d0.y + eA0.z * d0.z + eA0.w * d0.w
                  + eB0.x * d1.x + eB0.y * d1.y + eB0.z * d1.z + eB0.w * d1.w;
        float scB = eA1.x * d0.x + eA1.y * d0.y + eA1.z * d0.z + eA1.w * d0.w
                  + eB1.x * d1.x + eB1.y * d1.y + eB1.z * d1.z + eB1.w * d1.w;

        #pragma unroll
        for (int off = 8; off >= 1; off >>= 1) {
            scA += __shfl_xor_sync(0xFFFFFFFFu, scA, off);
            scB += __shfl_xor_sync(0xFFFFFFFFu, scB, off);
        }

        if (i == 0) {
            s_scores[t * TROWS + 4 * w + sub]     = scA;
            s_scores[t * TROWS + 4 * w + 2 + sub] = scB;
        }

        if (scA > m) {
            float cs = __expf(m - scA);             // exp(-inf)=0 first time
            m = scA; l *= cs;
            acc0.x *= cs; acc0.y *= cs; acc0.z *= cs; acc0.w *= cs;
            acc1.x *= cs; acc1.y *= cs; acc1.z *= cs; acc1.w *= cs;
        }
        float pA = __expf(scA - m);
        l += pA;
        acc0.x += pA * eA0.x; acc0.y += pA * eA0.y;
        acc0.z += pA * eA0.z; acc0.w += pA * eA0.w;
        acc1.x += pA * eB0.x; acc1.y += pA * eB0.y;
        acc1.z += pA * eB0.z; acc1.w += pA * eB0.w;

        if (scB > m) {
            float cs = __expf(m - scB);
            m = scB; l *= cs;
            acc0.x *= cs; acc0.y *= cs; acc0.z *= cs; acc0.w *= cs;
            acc1.x *= cs; acc1.y *= cs; acc1.z *= cs; acc1.w *= cs;
        }
        float pB = __expf(scB - m);
        l += pB;
        acc0.x += pB * eA1.x; acc0.y += pB * eA1.y;
        acc0.z += pB * eA1.z; acc0.w += pB * eA1.w;
        acc1.x += pB * eB1.x; acc1.y += pB * eB1.y;
        acc1.z += pB * eB1.z; acc1.w += pB * eB1.w;

        __syncthreads();                            // stage recyclable
        if (++stg == STAGES) { stg = 0; ph ^= 1; }
    }

    // ---- cross-sub combine (one butterfly level) ----
    float m_o = __shfl_xor_sync(0xFFFFFFFFu, m, 16);
    float l_o = __shfl_xor_sync(0xFFFFFFFFu, l, 16);
    float Mw = fmaxf(m, m_o);
    float sSelf  = __expf(m - Mw);
    float sOther = __expf(m_o - Mw);
    float Lw = l * sSelf + l_o * sOther;

    float t2;
    t2 = __shfl_xor_sync(0xFFFFFFFFu, acc0.x, 16); acc0.x = acc0.x * sSelf + t2 * sOther;
    t2 = __shfl_xor_sync(0xFFFFFFFFu, acc0.y, 16); acc0.y = acc0.y * sSelf + t2 * sOther;
    t2 = __shfl_xor_sync(0xFFFFFFFFu, acc0.z, 16); acc0.z = acc0.z * sSelf + t2 * sOther;
    t2 = __shfl_xor_sync(0xFFFFFFFFu, acc0.w, 16); acc0.w = acc0.w * sSelf + t2 * sOther;
    t2 = __shfl_xor_sync(0xFFFFFFFFu, acc1.x, 16); acc1.x = acc1.x * sSelf + t2 * sOther;
    t2 = __shfl_xor_sync(0xFFFFFFFFu, acc1.y, 16); acc1.y = acc1.y * sSelf + t2 * sOther;
    t2 = __shfl_xor_sync(0xFFFFFFFFu, acc1.z, 16); acc1.z = acc1.z * sSelf + t2 * sOther;
    t2 = __shfl_xor_sync(0xFFFFFFFFu, acc1.w, 16); acc1.w = acc1.w * sSelf + t2 * sOther;

    if (sub == 0) {
        *reinterpret_cast<float4*>(&s_acc[w * HID + i * 4])      = acc0;
        *reinterpret_cast<float4*>(&s_acc[w * HID + 64 + i * 4]) = acc1;
    }
    if (lane == 0) { s_m[w] = Mw; s_l[w] = Lw; }
    __syncthreads();

    // ---- CTA combine (redundant per thread) ----
    float M = -CUDART_INF_F;
    #pragma unroll
    for (int j = 0; j < WARPS; ++j) M = fmaxf(M, s_m[j]);
    float L = 0.0f;
    #pragma unroll
    for (int j = 0; j < WARPS; ++j) L += s_l[j] * __expf(s_m[j] - M);
    const float invL = 1.0f / L;

    if (tid < HID) {
        float c = 0.0f;
        #pragma unroll
        for (int j = 0; j < WARPS; ++j) c += s_acc[j * HID + tid] * __expf(s_m[j] - M);
        ctx[(size_t)b * HID + tid] = c * invL;
    }

    // attn probs: one float4 per thread, coalesced
    {
        float4 v = *reinterpret_cast<const float4*>(&s_scores[tid * 4]);
        v.x = __expf(v.x - M) * invL;
        v.y = __expf(v.y - M) * invL;
        v.z = __expf(v.z - M) * invL;
        v.w = __expf(v.w - M) * invL;
        *reinterpret_cast<float4*>(attn + (size_t)b * SEQ + tid * 4) = v;
    }
}

extern "C" void kernel_launch(void* const* d_in, const int* in_sizes, int n_in,
                              void* d_out, int out_size)
{
    const float* dec = (const float*)d_in[0];
    const float* enc = (const float*)d_in[1];
    if (n_in >= 2 && in_sizes[0] > in_sizes[1]) {
        dec = (const float*)d_in[1];
        enc = (const float*)d_in[0];
    }

    float* attn = (float*)d_out;                   // [BS, SEQ]
    float* ctx  = attn + (size_t)BS * SEQ;         // [BS, HID]

    cudaFuncSetAttribute(seq2seq_attn_kernel,
                         cudaFuncAttributeMaxDynamicSharedMemorySize,
                         (int)SMEM_BYTES);

    seq2seq_attn_kernel<<<BS, THREADS, SMEM_BYTES>>>(dec, enc, attn, ctx);
}